// round 2
// baseline (speedup 1.0000x reference)
#include <cuda_runtime.h>

// Problem constants (fixed shapes for TrivialDecoder_1236950581455)
#define E_GROUPS 65536
#define KNEG     16
#define GROUP    (KNEG + 1)                 // 17
#define PAIRS    (E_GROUPS * GROUP)         // 1,114,112
#define D        64
#define KDIM     192                        // 3*D
#define M_TILE   128
#define XSTR     196                        // padded row stride for Xs (float4-aligned)
#define THREADS  256

// Scratch for per-pair scores (static device array: no allocation in kernel_launch)
__device__ float g_scores[PAIRS];

__global__ void zero_out_kernel(float* out) { out[0] = 0.0f; }

// ---------------------------------------------------------------------------
// Kernel 1: fused gather + MLP, writes exp(sigmoid(mlp(x))) per pair.
// Block = 128 pairs, 256 threads. Shared: Xs[128][XSTR] + Ws[192][64] (W1^T).
// Warp w covers m-rows [16w, 16w+16), all 64 n; lane owns n = {2l, 2l+1}.
// ---------------------------------------------------------------------------
__global__ void __launch_bounds__(THREADS)
score_kernel(const float* __restrict__ embeds,
             const int*   __restrict__ pos,    // int32 indices (JAX x64 disabled)
             const int*   __restrict__ neg,
             const float* __restrict__ W1,
             const float* __restrict__ b1,
             const float* __restrict__ W2,
             const float* __restrict__ b2)
{
    extern __shared__ float smem[];
    float* Xs = smem;                    // [M_TILE][XSTR]
    float* Ws = smem + M_TILE * XSTR;    // [KDIM][D]  (Ws[k][n] = W1[n][k])

    const int tid = threadIdx.x;
    const int p0  = blockIdx.x * M_TILE;

    // Stage W1 transposed into shared: coalesced global reads, scattered STS.
    for (int idx = tid; idx < D * KDIM; idx += THREADS) {
        int n = idx / KDIM;
        int k = idx - n * KDIM;
        Ws[k * D + n] = W1[idx];
    }

    // Gather phase: 2 threads per pair-row; each handles 32 of the 64 dims.
    {
        int m    = tid >> 1;
        int half = tid & 1;
        int p    = p0 + m;
        unsigned e = (unsigned)p / 17u;
        unsigned j = (unsigned)p - e * 17u;
        const int* pr = (j == 0)
            ? (pos + 2 * e)
            : (neg + 2 * (e * KNEG + (j - 1)));
        long long iu = pr[0];
        long long iv = pr[1];
        const float4* up = (const float4*)(embeds + iu * 64) + half * 8;
        const float4* vp = (const float4*)(embeds + iv * 64) + half * 8;
        float* xr = Xs + m * XSTR + half * 32;
        #pragma unroll
        for (int q = 0; q < 8; q++) {
            float4 u = up[q];
            float4 v = vp[q];
            *(float4*)(xr +       4 * q) = u;
            *(float4*)(xr +  64 + 4 * q) = v;
            float4 uv = make_float4(u.x * v.x, u.y * v.y, u.z * v.z, u.w * v.w);
            *(float4*)(xr + 128 + 4 * q) = uv;
        }
    }
    __syncthreads();

    const int w  = tid >> 5;     // warp 0..7
    const int l  = tid & 31;     // lane
    const int m0 = w * 16;       // 16 m-rows per warp
    const int n0 = 2 * l;        // 2 n-cols per lane

    float acc[16][2];
    #pragma unroll
    for (int im = 0; im < 16; im++) { acc[im][0] = 0.0f; acc[im][1] = 0.0f; }

    // Main GEMM loop: FFMA-pipe-bound. x-loads are warp-uniform broadcasts.
    #pragma unroll 2
    for (int kk = 0; kk < KDIM; kk += 2) {
        float2 w0 = *(const float2*)(Ws + (kk    ) * D + n0);
        float2 w1 = *(const float2*)(Ws + (kk + 1) * D + n0);
        #pragma unroll
        for (int im = 0; im < 16; im++) {
            float2 x = *(const float2*)(Xs + (m0 + im) * XSTR + kk);
            acc[im][0] += x.x * w0.x;
            acc[im][1] += x.x * w0.y;
            acc[im][0] += x.y * w1.x;
            acc[im][1] += x.y * w1.y;
        }
    }

    // Epilogue: bias + ReLU + W2 dot, cross-lane reduce, sigmoid, exp.
    float b10 = b1[n0], b11 = b1[n0 + 1];
    float w20 = W2[n0], w21 = W2[n0 + 1];
    float b2v = b2[0];

    float zred = 0.0f;
    #pragma unroll
    for (int im = 0; im < 16; im++) {
        float h0 = acc[im][0] + b10; h0 = h0 > 0.0f ? h0 : 0.0f;
        float h1 = acc[im][1] + b11; h1 = h1 > 0.0f ? h1 : 0.0f;
        float v = h0 * w20 + h1 * w21;
        v += __shfl_xor_sync(0xffffffffu, v, 16);
        v += __shfl_xor_sync(0xffffffffu, v, 8);
        v += __shfl_xor_sync(0xffffffffu, v, 4);
        v += __shfl_xor_sync(0xffffffffu, v, 2);
        v += __shfl_xor_sync(0xffffffffu, v, 1);
        if (l == im) zred = v;
    }
    if (l < 16) {
        float z   = zred + b2v;
        float sig = 1.0f / (1.0f + expf(-z));
        g_scores[p0 + m0 + l] = expf(sig);
    }
}

// ---------------------------------------------------------------------------
// Kernel 2: per-group ratio + global reduction. One thread per group.
// ---------------------------------------------------------------------------
__global__ void __launch_bounds__(256)
loss_kernel(float* __restrict__ out)
{
    int e = blockIdx.x * blockDim.x + threadIdx.x;
    float term = 0.0f;
    if (e < E_GROUPS) {
        const float* s = g_scores + (long long)e * GROUP;
        float ps = s[0];
        float denom = ps;
        #pragma unroll
        for (int j = 1; j < GROUP; j++) denom += s[j];
        term = ps / (denom + 1e-8f) + 1e-8f;
    }
    // warp reduce
    #pragma unroll
    for (int o = 16; o; o >>= 1) term += __shfl_xor_sync(0xffffffffu, term, o);

    __shared__ float wsum[8];
    int l = threadIdx.x & 31;
    int w = threadIdx.x >> 5;
    if (l == 0) wsum[w] = term;
    __syncthreads();
    if (threadIdx.x < 8) {
        float t = wsum[threadIdx.x];
        #pragma unroll
        for (int o = 4; o; o >>= 1) t += __shfl_xor_sync(0x000000ffu, t, o);
        if (threadIdx.x == 0) atomicAdd(out, -t);
    }
}

extern "C" void kernel_launch(void* const* d_in, const int* in_sizes, int n_in,
                              void* d_out, int out_size)
{
    const float* embeds = (const float*)d_in[0];
    const int*   pos    = (const int*)  d_in[1];
    const int*   neg    = (const int*)  d_in[2];
    const float* W1     = (const float*)d_in[3];
    const float* b1     = (const float*)d_in[4];
    const float* W2     = (const float*)d_in[5];
    const float* b2     = (const float*)d_in[6];
    float*       out    = (float*)d_out;

    const size_t smem_bytes = (size_t)(M_TILE * XSTR + KDIM * D) * sizeof(float); // ~149.5 KB
    cudaFuncSetAttribute(score_kernel, cudaFuncAttributeMaxDynamicSharedMemorySize,
                         (int)smem_bytes);

    zero_out_kernel<<<1, 1>>>(out);
    score_kernel<<<PAIRS / M_TILE, THREADS, smem_bytes>>>(embeds, pos, neg, W1, b1, W2, b2);
    loss_kernel<<<E_GROUPS / 256, 256>>>(out);
}

// round 5
// speedup vs baseline: 4.4477x; 4.4477x over previous
#include <cuda_runtime.h>
#include <cuda_bf16.h>
#include <cstdint>

// Problem constants (fixed shapes for TrivialDecoder_1236950581455)
#define E_GROUPS 65536
#define KNEG     16
#define GROUP    17
#define PAIRS    (E_GROUPS * GROUP)   // 1,114,112
#define D        64
#define KDIM     192
#define M_TILE   128
#define THREADS  256
#define KSTEPS   12                   // 192 / 16
#define NTILES   8                    // 64 / 8

#define XPITCH   200                  // bf16 elems per SMEM row (400 B, odd 16B stride)

// SMEM byte layout
#define SMEM_B1    0                         // 64 floats
#define SMEM_W2    256                       // 64 floats
#define SMEM_A     1024                      // 128 x XPITCH bf16 = 51200 B
#define SMEM_B     (1024 + 128 * XPITCH * 2) // 64 x XPITCH bf16 = 25600 B
#define SMEM_TOTAL (SMEM_B + 64 * XPITCH * 2)

__device__ float g_scores[PAIRS];

__global__ void zero_out_kernel(float* out) { out[0] = 0.0f; }

// ---------------- portable PTX helpers ----------------
__device__ __forceinline__ uint32_t smem_u32(const void* p) {
    uint32_t a;
    asm("{ .reg .u64 t; cvta.to.shared.u64 t, %1; cvt.u32.u64 %0, t; }" : "=r"(a) : "l"(p));
    return a;
}

__device__ __forceinline__ void ldmatrix_x4(uint32_t* r, uint32_t addr) {
    asm volatile("ldmatrix.sync.aligned.m8n8.x4.shared.b16 {%0,%1,%2,%3}, [%4];"
                 : "=r"(r[0]), "=r"(r[1]), "=r"(r[2]), "=r"(r[3]) : "r"(addr));
}
__device__ __forceinline__ void ldmatrix_x2(uint32_t* r, uint32_t addr) {
    asm volatile("ldmatrix.sync.aligned.m8n8.x2.shared.b16 {%0,%1}, [%2];"
                 : "=r"(r[0]), "=r"(r[1]) : "r"(addr));
}
__device__ __forceinline__ void mma_16816(float* c, const uint32_t* a, const uint32_t* b) {
    asm volatile(
        "mma.sync.aligned.m16n8k16.row.col.f32.bf16.bf16.f32 "
        "{%0,%1,%2,%3}, {%4,%5,%6,%7}, {%8,%9}, {%0,%1,%2,%3};"
        : "+f"(c[0]), "+f"(c[1]), "+f"(c[2]), "+f"(c[3])
        : "r"(a[0]), "r"(a[1]), "r"(a[2]), "r"(a[3]), "r"(b[0]), "r"(b[1]));
}

__device__ __forceinline__ uint32_t pack2(float a, float b) {
    __nv_bfloat162 h = __float22bfloat162_rn(make_float2(a, b));
    return *reinterpret_cast<uint32_t*>(&h);
}

// ---------------------------------------------------------------------------
// Kernel 1: gather -> bf16 SMEM -> mma.sync GEMM -> fused epilogue -> scores
// Block = 128 pairs, 256 threads. Warp w owns m-rows [16w, 16w+16).
// ---------------------------------------------------------------------------
__global__ void __launch_bounds__(THREADS)
score_kernel(const float* __restrict__ embeds,
             const int*   __restrict__ pos,
             const int*   __restrict__ neg,
             const float* __restrict__ W1,
             const float* __restrict__ b1,
             const float* __restrict__ W2,
             const float* __restrict__ b2)
{
    extern __shared__ char smem[];
    const uint32_t sbase = smem_u32(smem);
    const int tid = threadIdx.x;
    const int wid = tid >> 5;
    const int lid = tid & 31;
    const int p0  = blockIdx.x * M_TILE;

    // Stage b1 / W2 to shared
    if (tid < 64) {
        ((float*)(smem + SMEM_B1))[tid] = b1[tid];
        ((float*)(smem + SMEM_W2))[tid] = W2[tid];
    }

    // Stage W1 ([64 n][192 k] fp32) -> bf16 SMEM rows of pitch XPITCH.
    for (int c = tid; c < 64 * 24; c += THREADS) {
        int n  = c / 24;
        int k0 = (c - n * 24) * 8;
        const float4* wp = (const float4*)(W1 + n * KDIM + k0);
        float4 w0 = wp[0], w1 = wp[1];
        uint4 v = make_uint4(pack2(w0.x, w0.y), pack2(w0.z, w0.w),
                             pack2(w1.x, w1.y), pack2(w1.z, w1.w));
        *(uint4*)(smem + SMEM_B + n * (XPITCH * 2) + k0 * 2) = v;
    }

    // Gather + convert: 2 threads per pair row, each handles 32 of 64 dims.
    {
        int m    = tid >> 1;
        int half = tid & 1;
        int p    = p0 + m;
        unsigned e = (unsigned)p / 17u;
        unsigned j = (unsigned)p - e * 17u;
        const int* pr = (j == 0) ? (pos + 2 * e)
                                 : (neg + 2 * (e * KNEG + (j - 1)));
        int iu = pr[0];
        int iv = pr[1];
        const float4* up = (const float4*)(embeds + (size_t)iu * 64) + half * 8;
        const float4* vp = (const float4*)(embeds + (size_t)iv * 64) + half * 8;
        char* xr = smem + SMEM_A + m * (XPITCH * 2);
        #pragma unroll
        for (int q = 0; q < 4; q++) {
            float4 ua = up[2 * q], ub = up[2 * q + 1];
            float4 va = vp[2 * q], vb = vp[2 * q + 1];
            int k0 = half * 32 + q * 8;
            uint4 us = make_uint4(pack2(ua.x, ua.y), pack2(ua.z, ua.w),
                                  pack2(ub.x, ub.y), pack2(ub.z, ub.w));
            uint4 vs = make_uint4(pack2(va.x, va.y), pack2(va.z, va.w),
                                  pack2(vb.x, vb.y), pack2(vb.z, vb.w));
            uint4 ws = make_uint4(pack2(ua.x * va.x, ua.y * va.y), pack2(ua.z * va.z, ua.w * va.w),
                                  pack2(ub.x * vb.x, ub.y * vb.y), pack2(ub.z * vb.z, ub.w * vb.w));
            *(uint4*)(xr + k0 * 2)         = us;   // u       -> k [0,64)
            *(uint4*)(xr + (64 + k0) * 2)  = vs;   // v       -> k [64,128)
            *(uint4*)(xr + (128 + k0) * 2) = ws;   // u*v     -> k [128,192)
        }
    }
    __syncthreads();

    // GEMM: warp tile 16(m) x 64(n), K=192. c[nt][4] fp32 accumulators.
    float c[NTILES][4];
    #pragma unroll
    for (int nt = 0; nt < NTILES; nt++) { c[nt][0] = c[nt][1] = c[nt][2] = c[nt][3] = 0.0f; }

    const uint32_t a_addr0 = sbase + SMEM_A
                           + (wid * 16 + (lid & 15)) * (XPITCH * 2) + (lid >> 4) * 16;
    const uint32_t b_addr0 = sbase + SMEM_B
                           + (lid & 7) * (XPITCH * 2) + ((lid >> 3) & 1) * 16;

    #pragma unroll
    for (int ks = 0; ks < KSTEPS; ks++) {
        uint32_t a[4];
        ldmatrix_x4(a, a_addr0 + ks * 32);
        #pragma unroll
        for (int nt = 0; nt < NTILES; nt++) {
            uint32_t b[2];
            ldmatrix_x2(b, b_addr0 + nt * 8 * (XPITCH * 2) + ks * 32);
            mma_16816(c[nt], a, b);
        }
    }

    // Epilogue in fragment layout: rows r0 = wid*16 + lid/4, r1 = r0 + 8.
    const float* b1s = (const float*)(smem + SMEM_B1);
    const float* w2s = (const float*)(smem + SMEM_W2);
    float z0 = 0.0f, z1 = 0.0f;
    #pragma unroll
    for (int nt = 0; nt < NTILES; nt++) {
        int n0 = nt * 8 + 2 * (lid & 3);
        float bb0 = b1s[n0], bb1 = b1s[n0 + 1];
        float ww0 = w2s[n0], ww1 = w2s[n0 + 1];
        float h;
        h = c[nt][0] + bb0; h = h > 0.0f ? h : 0.0f; z0 += h * ww0;
        h = c[nt][1] + bb1; h = h > 0.0f ? h : 0.0f; z0 += h * ww1;
        h = c[nt][2] + bb0; h = h > 0.0f ? h : 0.0f; z1 += h * ww0;
        h = c[nt][3] + bb1; h = h > 0.0f ? h : 0.0f; z1 += h * ww1;
    }
    // Reduce across the 4 lanes of each column group.
    z0 += __shfl_xor_sync(0xffffffffu, z0, 1);
    z0 += __shfl_xor_sync(0xffffffffu, z0, 2);
    z1 += __shfl_xor_sync(0xffffffffu, z1, 1);
    z1 += __shfl_xor_sync(0xffffffffu, z1, 2);

    if ((lid & 3) == 0) {
        float b2v = b2[0];
        int r = p0 + wid * 16 + (lid >> 2);
        float s0 = 1.0f / (1.0f + expf(-(z0 + b2v)));
        float s1 = 1.0f / (1.0f + expf(-(z1 + b2v)));
        g_scores[r]     = expf(s0);
        g_scores[r + 8] = expf(s1);
    }
}

// ---------------------------------------------------------------------------
// Kernel 2: per-group ratio + global reduction.
// ---------------------------------------------------------------------------
__global__ void __launch_bounds__(256)
loss_kernel(float* __restrict__ out)
{
    int e = blockIdx.x * blockDim.x + threadIdx.x;
    float term = 0.0f;
    if (e < E_GROUPS) {
        const float* s = g_scores + (long long)e * GROUP;
        float ps = s[0];
        float denom = ps;
        #pragma unroll
        for (int j = 1; j < GROUP; j++) denom += s[j];
        term = ps / (denom + 1e-8f) + 1e-8f;
    }
    #pragma unroll
    for (int o = 16; o; o >>= 1) term += __shfl_xor_sync(0xffffffffu, term, o);

    __shared__ float wsum[8];
    int l = threadIdx.x & 31;
    int w = threadIdx.x >> 5;
    if (l == 0) wsum[w] = term;
    __syncthreads();
    if (threadIdx.x < 8) {
        float t = wsum[threadIdx.x];
        #pragma unroll
        for (int o = 4; o; o >>= 1) t += __shfl_xor_sync(0x000000ffu, t, o);
        if (threadIdx.x == 0) atomicAdd(out, -t);
    }
}

extern "C" void kernel_launch(void* const* d_in, const int* in_sizes, int n_in,
                              void* d_out, int out_size)
{
    const float* embeds = (const float*)d_in[0];
    const int*   pos    = (const int*)  d_in[1];
    const int*   neg    = (const int*)  d_in[2];
    const float* W1     = (const float*)d_in[3];
    const float* b1     = (const float*)d_in[4];
    const float* W2     = (const float*)d_in[5];
    const float* b2     = (const float*)d_in[6];
    float*       out    = (float*)d_out;

    cudaFuncSetAttribute(score_kernel, cudaFuncAttributeMaxDynamicSharedMemorySize,
                         SMEM_TOTAL);

    zero_out_kernel<<<1, 1>>>(out);
    score_kernel<<<PAIRS / M_TILE, THREADS, SMEM_TOTAL>>>(embeds, pos, neg, W1, b1, W2, b2);
    loss_kernel<<<E_GROUPS / 256, 256>>>(out);
}

// round 6
// speedup vs baseline: 6.1403x; 1.3806x over previous
#include <cuda_runtime.h>
#include <cuda_bf16.h>
#include <cstdint>

// Problem constants (fixed shapes for TrivialDecoder_1236950581455)
#define E_GROUPS 65536
#define KNEG     16
#define GROUP    17
#define PAIRS    (E_GROUPS * GROUP)   // 1,114,112
#define D        64
#define KDIM     192
#define M_TILE   128
#define THREADS  256
#define KSTEPS   12                   // 192 / 16
#define NTILES   8                    // 64 / 8

#define XPITCH   200                  // bf16 elems per SMEM row (400 B, odd 16B stride)

// SMEM byte layout
#define SMEM_B1    0                         // 64 floats
#define SMEM_W2    256                       // 64 floats
#define SMEM_A     1024                      // 128 x XPITCH bf16 = 51200 B
#define SMEM_B     (1024 + 128 * XPITCH * 2) // 64 x XPITCH bf16 = 25600 B
#define SMEM_TOTAL (SMEM_B + 64 * XPITCH * 2)

__device__ float g_scores[PAIRS];

__global__ void zero_out_kernel(float* out) { out[0] = 0.0f; }

// ---------------- portable PTX helpers ----------------
__device__ __forceinline__ uint32_t smem_u32(const void* p) {
    uint32_t a;
    asm("{ .reg .u64 t; cvta.to.shared.u64 t, %1; cvt.u32.u64 %0, t; }" : "=r"(a) : "l"(p));
    return a;
}

__device__ __forceinline__ void ldmatrix_x4(uint32_t* r, uint32_t addr) {
    asm volatile("ldmatrix.sync.aligned.m8n8.x4.shared.b16 {%0,%1,%2,%3}, [%4];"
                 : "=r"(r[0]), "=r"(r[1]), "=r"(r[2]), "=r"(r[3]) : "r"(addr));
}
__device__ __forceinline__ void ldmatrix_x2(uint32_t* r, uint32_t addr) {
    asm volatile("ldmatrix.sync.aligned.m8n8.x2.shared.b16 {%0,%1}, [%2];"
                 : "=r"(r[0]), "=r"(r[1]) : "r"(addr));
}
__device__ __forceinline__ void mma_16816(float* c, const uint32_t* a, const uint32_t* b) {
    asm volatile(
        "mma.sync.aligned.m16n8k16.row.col.f32.bf16.bf16.f32 "
        "{%0,%1,%2,%3}, {%4,%5,%6,%7}, {%8,%9}, {%0,%1,%2,%3};"
        : "+f"(c[0]), "+f"(c[1]), "+f"(c[2]), "+f"(c[3])
        : "r"(a[0]), "r"(a[1]), "r"(a[2]), "r"(a[3]), "r"(b[0]), "r"(b[1]));
}

__device__ __forceinline__ uint32_t pack2(float a, float b) {
    __nv_bfloat162 h = __float22bfloat162_rn(make_float2(a, b));
    return *reinterpret_cast<uint32_t*>(&h);
}

// ---------------------------------------------------------------------------
// Kernel 1: gather -> bf16 SMEM -> mma.sync GEMM -> fused epilogue -> scores
// Block = 128 pairs, 256 threads. Warp w owns m-rows [16w, 16w+16).
// Gather: 16 lanes cover one 256B embedding row (fully coalesced LDG.128).
// ---------------------------------------------------------------------------
__global__ void __launch_bounds__(THREADS)
score_kernel(const float* __restrict__ embeds,
             const int*   __restrict__ pos,
             const int*   __restrict__ neg,
             const float* __restrict__ W1,
             const float* __restrict__ b1,
             const float* __restrict__ W2,
             const float* __restrict__ b2)
{
    extern __shared__ char smem[];
    const uint32_t sbase = smem_u32(smem);
    const int tid = threadIdx.x;
    const int wid = tid >> 5;
    const int lid = tid & 31;
    const int p0  = blockIdx.x * M_TILE;

    // Stage b1 / W2 to shared
    if (tid < 64) {
        ((float*)(smem + SMEM_B1))[tid] = b1[tid];
        ((float*)(smem + SMEM_W2))[tid] = W2[tid];
    }

    // Stage W1 ([64 n][192 k] fp32) -> bf16 SMEM rows of pitch XPITCH.
    for (int c = tid; c < 64 * 24; c += THREADS) {
        int n  = c / 24;
        int k0 = (c - n * 24) * 8;
        const float4* wp = (const float4*)(W1 + n * KDIM + k0);
        float4 w0 = wp[0], w1 = wp[1];
        uint4 v = make_uint4(pack2(w0.x, w0.y), pack2(w0.z, w0.w),
                             pack2(w1.x, w1.y), pack2(w1.z, w1.w));
        *(uint4*)(smem + SMEM_B + n * (XPITCH * 2) + k0 * 2) = v;
    }

    // Gather + convert: warp handles its 16 m-rows; per iteration two rows,
    // 16 lanes each (lane covers one float4 slot of the 256B row).
    {
        int q   = lid & 15;          // float4 index within the 64-float row
        int grp = lid >> 4;          // 0 or 1: which of the two rows this iter

        // lanes 0..15 preload (iu, iv) for local rows 0..15
        int iu_r = 0, iv_r = 0;
        if (lid < 16) {
            int p = p0 + wid * 16 + lid;
            unsigned e = (unsigned)p / 17u;
            unsigned j = (unsigned)p - e * 17u;
            const int* pr = (j == 0) ? (pos + 2 * e)
                                     : (neg + 2 * (e * KNEG + (j - 1)));
            iu_r = pr[0];
            iv_r = pr[1];
        }

        #pragma unroll
        for (int it = 0; it < 8; it++) {
            int src = 2 * it + grp;                      // local row 0..15
            int iu = __shfl_sync(0xffffffffu, iu_r, src);
            int iv = __shfl_sync(0xffffffffu, iv_r, src);
            float4 u4 = ((const float4*)(embeds + (size_t)iu * 64))[q];
            float4 v4 = ((const float4*)(embeds + (size_t)iv * 64))[q];
            char* xr = smem + SMEM_A + (wid * 16 + src) * (XPITCH * 2);
            *(uint2*)(xr + q * 8) =
                make_uint2(pack2(u4.x, u4.y), pack2(u4.z, u4.w));
            *(uint2*)(xr + 128 + q * 8) =
                make_uint2(pack2(v4.x, v4.y), pack2(v4.z, v4.w));
            *(uint2*)(xr + 256 + q * 8) =
                make_uint2(pack2(u4.x * v4.x, u4.y * v4.y),
                           pack2(u4.z * v4.z, u4.w * v4.w));
        }
    }
    __syncthreads();

    // GEMM: warp tile 16(m) x 64(n), K=192. c[nt][4] fp32 accumulators.
    float c[NTILES][4];
    #pragma unroll
    for (int nt = 0; nt < NTILES; nt++) { c[nt][0] = c[nt][1] = c[nt][2] = c[nt][3] = 0.0f; }

    const uint32_t a_addr0 = sbase + SMEM_A
                           + (wid * 16 + (lid & 15)) * (XPITCH * 2) + (lid >> 4) * 16;
    const uint32_t b_addr0 = sbase + SMEM_B
                           + (lid & 7) * (XPITCH * 2) + ((lid >> 3) & 1) * 16;

    #pragma unroll
    for (int ks = 0; ks < KSTEPS; ks++) {
        uint32_t a[4];
        ldmatrix_x4(a, a_addr0 + ks * 32);
        #pragma unroll
        for (int nt = 0; nt < NTILES; nt++) {
            uint32_t b[2];
            ldmatrix_x2(b, b_addr0 + nt * 8 * (XPITCH * 2) + ks * 32);
            mma_16816(c[nt], a, b);
        }
    }

    // Epilogue in fragment layout: rows r0 = wid*16 + lid/4, r1 = r0 + 8.
    const float* b1s = (const float*)(smem + SMEM_B1);
    const float* w2s = (const float*)(smem + SMEM_W2);
    float z0 = 0.0f, z1 = 0.0f;
    #pragma unroll
    for (int nt = 0; nt < NTILES; nt++) {
        int n0 = nt * 8 + 2 * (lid & 3);
        float bb0 = b1s[n0], bb1 = b1s[n0 + 1];
        float ww0 = w2s[n0], ww1 = w2s[n0 + 1];
        float h;
        h = c[nt][0] + bb0; h = h > 0.0f ? h : 0.0f; z0 += h * ww0;
        h = c[nt][1] + bb1; h = h > 0.0f ? h : 0.0f; z0 += h * ww1;
        h = c[nt][2] + bb0; h = h > 0.0f ? h : 0.0f; z1 += h * ww0;
        h = c[nt][3] + bb1; h = h > 0.0f ? h : 0.0f; z1 += h * ww1;
    }
    // Reduce across the 4 lanes of each column group.
    z0 += __shfl_xor_sync(0xffffffffu, z0, 1);
    z0 += __shfl_xor_sync(0xffffffffu, z0, 2);
    z1 += __shfl_xor_sync(0xffffffffu, z1, 1);
    z1 += __shfl_xor_sync(0xffffffffu, z1, 2);

    if ((lid & 3) == 0) {
        float b2v = b2[0];
        int r = p0 + wid * 16 + (lid >> 2);
        float s0 = 1.0f / (1.0f + expf(-(z0 + b2v)));
        float s1 = 1.0f / (1.0f + expf(-(z1 + b2v)));
        g_scores[r]     = expf(s0);
        g_scores[r + 8] = expf(s1);
    }
}

// ---------------------------------------------------------------------------
// Kernel 2: per-group ratio + global reduction.
// ---------------------------------------------------------------------------
__global__ void __launch_bounds__(256)
loss_kernel(float* __restrict__ out)
{
    int e = blockIdx.x * blockDim.x + threadIdx.x;
    float term = 0.0f;
    if (e < E_GROUPS) {
        const float* s = g_scores + (long long)e * GROUP;
        float ps = s[0];
        float denom = ps;
        #pragma unroll
        for (int j = 1; j < GROUP; j++) denom += s[j];
        term = ps / (denom + 1e-8f) + 1e-8f;
    }
    #pragma unroll
    for (int o = 16; o; o >>= 1) term += __shfl_xor_sync(0xffffffffu, term, o);

    __shared__ float wsum[8];
    int l = threadIdx.x & 31;
    int w = threadIdx.x >> 5;
    if (l == 0) wsum[w] = term;
    __syncthreads();
    if (threadIdx.x < 8) {
        float t = wsum[threadIdx.x];
        #pragma unroll
        for (int o = 4; o; o >>= 1) t += __shfl_xor_sync(0x000000ffu, t, o);
        if (threadIdx.x == 0) atomicAdd(out, -t);
    }
}

extern "C" void kernel_launch(void* const* d_in, const int* in_sizes, int n_in,
                              void* d_out, int out_size)
{
    const float* embeds = (const float*)d_in[0];
    const int*   pos    = (const int*)  d_in[1];
    const int*   neg    = (const int*)  d_in[2];
    const float* W1     = (const float*)d_in[3];
    const float* b1     = (const float*)d_in[4];
    const float* W2     = (const float*)d_in[5];
    const float* b2     = (const float*)d_in[6];
    float*       out    = (float*)d_out;

    cudaFuncSetAttribute(score_kernel, cudaFuncAttributeMaxDynamicSharedMemorySize,
                         SMEM_TOTAL);

    zero_out_kernel<<<1, 1>>>(out);
    score_kernel<<<PAIRS / M_TILE, THREADS, SMEM_TOTAL>>>(embeds, pos, neg, W1, b1, W2, b2);
    loss_kernel<<<E_GROUPS / 256, 256>>>(out);
}

// round 7
// speedup vs baseline: 8.5240x; 1.3882x over previous
#include <cuda_runtime.h>
#include <cuda_bf16.h>
#include <cstdint>

// Problem constants (fixed shapes for TrivialDecoder_1236950581455)
#define E_GROUPS 65536
#define KNEG     16
#define GROUP    17
#define PAIRS    (E_GROUPS * GROUP)   // 1,114,112
#define D        64
#define KDIM     192
#define M_TILE   128
#define NTILE_TOT (PAIRS / M_TILE)    // 8704
#define THREADS  256
#define KSTEPS   12                   // 192 / 16
#define NTILES   8                    // 64 / 8
#define GRID_SC  444                  // 148 SMs x 3 CTAs

#define XPITCH   200                  // A: bf16 elems per row (400 B, conflict-free)
#define BPITCH_B 384                  // B: bytes per row (swizzled chunks)

// SMEM byte layout (total 76800 B = 75 KB -> 3 CTAs/SM incl. 1KB/CTA reserve)
#define SMEM_B1    0                          // 64 floats
#define SMEM_W2    256                        // 64 floats
#define SMEM_A     1024                       // 128 x 400 B = 51200 B
#define SMEM_B     (1024 + 128 * XPITCH * 2)  // 64 x 384 B = 24576 B
#define SMEM_TOTAL (SMEM_B + 64 * BPITCH_B)   // 76800

__device__ float g_scores[PAIRS];

__global__ void zero_out_kernel(float* out) { out[0] = 0.0f; }

// ---------------- portable PTX helpers ----------------
__device__ __forceinline__ uint32_t smem_u32(const void* p) {
    uint32_t a;
    asm("{ .reg .u64 t; cvta.to.shared.u64 t, %1; cvt.u32.u64 %0, t; }" : "=r"(a) : "l"(p));
    return a;
}

__device__ __forceinline__ void ldmatrix_x4(uint32_t* r, uint32_t addr) {
    asm volatile("ldmatrix.sync.aligned.m8n8.x4.shared.b16 {%0,%1,%2,%3}, [%4];"
                 : "=r"(r[0]), "=r"(r[1]), "=r"(r[2]), "=r"(r[3]) : "r"(addr));
}
__device__ __forceinline__ void ldmatrix_x2(uint32_t* r, uint32_t addr) {
    asm volatile("ldmatrix.sync.aligned.m8n8.x2.shared.b16 {%0,%1}, [%2];"
                 : "=r"(r[0]), "=r"(r[1]) : "r"(addr));
}
__device__ __forceinline__ void mma_16816(float* c, const uint32_t* a, const uint32_t* b) {
    asm volatile(
        "mma.sync.aligned.m16n8k16.row.col.f32.bf16.bf16.f32 "
        "{%0,%1,%2,%3}, {%4,%5,%6,%7}, {%8,%9}, {%0,%1,%2,%3};"
        : "+f"(c[0]), "+f"(c[1]), "+f"(c[2]), "+f"(c[3])
        : "r"(a[0]), "r"(a[1]), "r"(a[2]), "r"(a[3]), "r"(b[0]), "r"(b[1]));
}

__device__ __forceinline__ uint32_t pack2(float a, float b) {
    __nv_bfloat162 h = __float22bfloat162_rn(make_float2(a, b));
    return *reinterpret_cast<uint32_t*>(&h);
}

// B tile swizzle: row n (384 B pitch), 16B-chunk index ch in [0,24): ch ^= (n & 7)
__device__ __forceinline__ int b_byte(int n, int ch) {
    return SMEM_B + n * BPITCH_B + ((ch ^ (n & 7)) << 4);
}

// ---------------------------------------------------------------------------
// Kernel 1: persistent, barrier-free warp pipelines.
// Each CTA stages W1/b1/W2 once, then loops over 128-pair tiles.
// Warp w owns m-rows [16w, 16w+16): it alone writes and reads those A rows,
// so no per-tile __syncthreads is needed.
// ---------------------------------------------------------------------------
__global__ void __launch_bounds__(THREADS, 3)
score_kernel(const float* __restrict__ embeds,
             const int*   __restrict__ pos,
             const int*   __restrict__ neg,
             const float* __restrict__ W1,
             const float* __restrict__ b1,
             const float* __restrict__ W2,
             const float* __restrict__ b2)
{
    extern __shared__ char smem[];
    const uint32_t sbase = smem_u32(smem);
    const int tid = threadIdx.x;
    const int wid = tid >> 5;
    const int lid = tid & 31;

    // One-time staging: b1, W2, W1 (bf16, swizzled B tile).
    if (tid < 64) {
        ((float*)(smem + SMEM_B1))[tid] = b1[tid];
        ((float*)(smem + SMEM_W2))[tid] = W2[tid];
    }
    for (int c = tid; c < 64 * 24; c += THREADS) {
        int n  = c / 24;
        int ch = c - n * 24;
        const float4* wp = (const float4*)(W1 + n * KDIM + ch * 8);
        float4 w0 = wp[0], w1 = wp[1];
        uint4 v = make_uint4(pack2(w0.x, w0.y), pack2(w0.z, w0.w),
                             pack2(w1.x, w1.y), pack2(w1.z, w1.w));
        *(uint4*)(smem + b_byte(n, ch)) = v;
    }
    __syncthreads();   // only barrier in the kernel

    const float b2v = b2[0];
    const int q   = lid & 15;          // float4 slot within a 64-float row
    const int grp = lid >> 4;          // which of two rows per gather iter

    const uint32_t a_addr0 = sbase + SMEM_A
                           + (wid * 16 + (lid & 15)) * (XPITCH * 2) + (lid >> 4) * 16;
    const uint32_t b_row0  = sbase + SMEM_B + (lid & 7) * BPITCH_B;
    const int      b_xor   = (lid & 7);
    const int      b_h     = (lid >> 3) & 1;

    char* xr_base = smem + SMEM_A + wid * 16 * (XPITCH * 2);

    for (int t = blockIdx.x; t < NTILE_TOT; t += GRID_SC) {
        const int p0 = t * M_TILE;

        // ---- gather + convert (warp-local rows) ----
        int iu_r = 0, iv_r = 0;
        if (lid < 16) {
            int p = p0 + wid * 16 + lid;
            unsigned e = (unsigned)p / 17u;
            unsigned j = (unsigned)p - e * 17u;
            const int* pr = (j == 0) ? (pos + 2 * e)
                                     : (neg + 2 * (e * KNEG + (j - 1)));
            iu_r = pr[0];
            iv_r = pr[1];
        }
        #pragma unroll
        for (int it = 0; it < 8; it++) {
            int src = 2 * it + grp;                       // local row 0..15
            int iu = __shfl_sync(0xffffffffu, iu_r, src);
            int iv = __shfl_sync(0xffffffffu, iv_r, src);
            float4 u4 = ((const float4*)(embeds + (size_t)iu * 64))[q];
            float4 v4 = ((const float4*)(embeds + (size_t)iv * 64))[q];
            char* xr = xr_base + src * (XPITCH * 2);
            *(uint2*)(xr + q * 8) =
                make_uint2(pack2(u4.x, u4.y), pack2(u4.z, u4.w));
            *(uint2*)(xr + 128 + q * 8) =
                make_uint2(pack2(v4.x, v4.y), pack2(v4.z, v4.w));
            *(uint2*)(xr + 256 + q * 8) =
                make_uint2(pack2(u4.x * v4.x, u4.y * v4.y),
                           pack2(u4.z * v4.z, u4.w * v4.w));
        }

        // ---- GEMM: warp tile 16(m) x 64(n), K=192 ----
        float c[NTILES][4];
        #pragma unroll
        for (int nt = 0; nt < NTILES; nt++) {
            c[nt][0] = c[nt][1] = c[nt][2] = c[nt][3] = 0.0f;
        }
        #pragma unroll
        for (int ks = 0; ks < KSTEPS; ks++) {
            uint32_t a[4];
            ldmatrix_x4(a, a_addr0 + ks * 32);
            const uint32_t b_choff = (uint32_t)(((ks * 2 + b_h) ^ b_xor) << 4);
            #pragma unroll
            for (int nt = 0; nt < NTILES; nt++) {
                uint32_t b[2];
                ldmatrix_x2(b, b_row0 + nt * 8 * BPITCH_B + b_choff);
                mma_16816(c[nt], a, b);
            }
        }

        // ---- epilogue in fragment layout ----
        const float* b1s = (const float*)(smem + SMEM_B1);
        const float* w2s = (const float*)(smem + SMEM_W2);
        float z0 = 0.0f, z1 = 0.0f;
        #pragma unroll
        for (int nt = 0; nt < NTILES; nt++) {
            int n0 = nt * 8 + 2 * (lid & 3);
            float bb0 = b1s[n0], bb1 = b1s[n0 + 1];
            float ww0 = w2s[n0], ww1 = w2s[n0 + 1];
            float h;
            h = c[nt][0] + bb0; h = h > 0.0f ? h : 0.0f; z0 += h * ww0;
            h = c[nt][1] + bb1; h = h > 0.0f ? h : 0.0f; z0 += h * ww1;
            h = c[nt][2] + bb0; h = h > 0.0f ? h : 0.0f; z1 += h * ww0;
            h = c[nt][3] + bb1; h = h > 0.0f ? h : 0.0f; z1 += h * ww1;
        }
        z0 += __shfl_xor_sync(0xffffffffu, z0, 1);
        z0 += __shfl_xor_sync(0xffffffffu, z0, 2);
        z1 += __shfl_xor_sync(0xffffffffu, z1, 1);
        z1 += __shfl_xor_sync(0xffffffffu, z1, 2);

        if ((lid & 3) == 0) {
            int r = p0 + wid * 16 + (lid >> 2);
            float s0 = 1.0f / (1.0f + expf(-(z0 + b2v)));
            float s1 = 1.0f / (1.0f + expf(-(z1 + b2v)));
            g_scores[r]     = expf(s0);
            g_scores[r + 8] = expf(s1);
        }
    }
}

// ---------------------------------------------------------------------------
// Kernel 2: per-group ratio + global reduction.
// ---------------------------------------------------------------------------
__global__ void __launch_bounds__(256)
loss_kernel(float* __restrict__ out)
{
    int e = blockIdx.x * blockDim.x + threadIdx.x;
    float term = 0.0f;
    if (e < E_GROUPS) {
        const float* s = g_scores + (long long)e * GROUP;
        float ps = s[0];
        float denom = ps;
        #pragma unroll
        for (int j = 1; j < GROUP; j++) denom += s[j];
        term = ps / (denom + 1e-8f) + 1e-8f;
    }
    #pragma unroll
    for (int o = 16; o; o >>= 1) term += __shfl_xor_sync(0xffffffffu, term, o);

    __shared__ float wsum[8];
    int l = threadIdx.x & 31;
    int w = threadIdx.x >> 5;
    if (l == 0) wsum[w] = term;
    __syncthreads();
    if (threadIdx.x < 8) {
        float t = wsum[threadIdx.x];
        #pragma unroll
        for (int o = 4; o; o >>= 1) t += __shfl_xor_sync(0x000000ffu, t, o);
        if (threadIdx.x == 0) atomicAdd(out, -t);
    }
}

extern "C" void kernel_launch(void* const* d_in, const int* in_sizes, int n_in,
                              void* d_out, int out_size)
{
    const float* embeds = (const float*)d_in[0];
    const int*   pos    = (const int*)  d_in[1];
    const int*   neg    = (const int*)  d_in[2];
    const float* W1     = (const float*)d_in[3];
    const float* b1     = (const float*)d_in[4];
    const float* W2     = (const float*)d_in[5];
    const float* b2     = (const float*)d_in[6];
    float*       out    = (float*)d_out;

    cudaFuncSetAttribute(score_kernel, cudaFuncAttributeMaxDynamicSharedMemorySize,
                         SMEM_TOTAL);

    zero_out_kernel<<<1, 1>>>(out);
    score_kernel<<<GRID_SC, THREADS, SMEM_TOTAL>>>(embeds, pos, neg, W1, b1, W2, b2);
    loss_kernel<<<E_GROUPS / 256, 256>>>(out);
}